// round 1
// baseline (speedup 1.0000x reference)
#include <cuda_runtime.h>
#include <math.h>

// Problem constants
#define BATCH 4
#define C 32
#define H 64
#define W 64
#define HW 4096            // 64*64
#define LSEQ 4096          // sequence length per batch (= C*H*W / 32)
#define GTOT 16384         // BATCH * LSEQ
#define DIN 64             // d_inner
#define DST 32             // d_state
#define DTR 2              // dt_rank
#define NPROJ 128          // 2*DIN
#define NXDBL 66           // DTR + 2*DST

// -------- device scratch (no cudaMalloc allowed) --------
__device__ float  g_t   [BATCH*64*HW];   // conv1 out (4,64,64,64)
__device__ float  g_x2  [BATCH*C*HW];    // conv2+res (also LN input, flat)
__device__ float  g_xs  [GTOT*C];        // layernorm out, rows of 32
__device__ float  g_xm  [GTOT*DIN];      // in_proj xm (pre-conv1d)
__device__ float  g_z   [GTOT*DIN];      // in_proj z
__device__ float  g_xm2 [GTOT*DIN];      // post conv1d + silu
__device__ float  g_dt  [GTOT*DTR];
__device__ float  g_Bm  [GTOT*DST];
__device__ float  g_Cm  [GTOT*DST];
__device__ float4 g_P   [GTOT*DIN];      // {delta, delta*xm, xm*Dp, silu(z)}
__device__ float  g_ys  [GTOT*DIN];      // scan output (pre out_proj)
__device__ float  g_yimg[BATCH*C*HW];    // out_proj out, (b,c,hw) layout

// ============================================================
// 3x3 conv, pad 1, direct. 32x32 tile/block, 2x2 px * 4 oc per thread.
// ============================================================
template<int IC, int OC, bool RELU, bool RES>
__global__ __launch_bounds__(256) void conv3x3_k(
    const float* __restrict__ in, const float* __restrict__ wt,
    const float* __restrict__ bias, const float* __restrict__ res,
    float* __restrict__ out)
{
    __shared__ float tile[34][35];
    const int tx = threadIdx.x, ty = threadIdx.y;
    const int tid = ty * 16 + tx;
    const int zb = blockIdx.z;
    const int b   = zb / (OC / 4);
    const int oc0 = (zb % (OC / 4)) * 4;
    const int x0 = blockIdx.x * 32, y0 = blockIdx.y * 32;

    float acc[4][2][2];
#pragma unroll
    for (int j = 0; j < 4; j++) {
        float bv = bias[oc0 + j];
        acc[j][0][0] = bv; acc[j][0][1] = bv; acc[j][1][0] = bv; acc[j][1][1] = bv;
    }

    for (int ic = 0; ic < IC; ic++) {
        const float* ip = in + ((long)(b * IC + ic) << 12);
        __syncthreads();
        for (int i = tid; i < 34 * 34; i += 256) {
            int r = i / 34, c = i % 34;
            int yy = y0 + r - 1, xx = x0 + c - 1;
            float v = 0.f;
            if ((unsigned)yy < 64u && (unsigned)xx < 64u) v = ip[(yy << 6) + xx];
            tile[r][c] = v;
        }
        __syncthreads();
        float dr[4][4];
#pragma unroll
        for (int r = 0; r < 4; r++)
#pragma unroll
            for (int c = 0; c < 4; c++) dr[r][c] = tile[ty * 2 + r][tx * 2 + c];
#pragma unroll
        for (int j = 0; j < 4; j++) {
            const float* wp = wt + ((long)((oc0 + j) * IC + ic)) * 9;
#pragma unroll
            for (int ky = 0; ky < 3; ky++)
#pragma unroll
                for (int kx = 0; kx < 3; kx++) {
                    float wv = __ldg(wp + ky * 3 + kx);
#pragma unroll
                    for (int pr = 0; pr < 2; pr++)
#pragma unroll
                        for (int pc = 0; pc < 2; pc++)
                            acc[j][pr][pc] = fmaf(dr[pr + ky][pc + kx], wv, acc[j][pr][pc]);
                }
        }
    }

#pragma unroll
    for (int j = 0; j < 4; j++) {
        int oc = oc0 + j;
#pragma unroll
        for (int pr = 0; pr < 2; pr++)
#pragma unroll
            for (int pc = 0; pc < 2; pc++) {
                int y = y0 + ty * 2 + pr, x = x0 + tx * 2 + pc;
                float v = acc[j][pr][pc];
                if (RELU) v = fmaxf(v, 0.f);
                long off = ((long)(b * OC + oc) << 12) + (y << 6) + x;
                if (RES) v += res[off];
                out[off] = v;
            }
    }
}

// ============================================================
// LayerNorm over groups of 32 consecutive floats (raw reshape semantics)
// ============================================================
__global__ __launch_bounds__(256) void ln_k(
    const float* __restrict__ x, const float* __restrict__ g,
    const float* __restrict__ bt, float* __restrict__ out)
{
    int warp = (blockIdx.x * blockDim.x + threadIdx.x) >> 5;
    int lane = threadIdx.x & 31;
    if (warp >= GTOT) return;
    float v = x[warp * 32 + lane];
    float s = v;
#pragma unroll
    for (int o = 16; o; o >>= 1) s += __shfl_xor_sync(0xffffffffu, s, o);
    float mu = s * (1.f / 32.f);
    float d = v - mu;
    float q = d * d;
#pragma unroll
    for (int o = 16; o; o >>= 1) q += __shfl_xor_sync(0xffffffffu, q, o);
    float var = q * (1.f / 32.f);
    out[warp * 32 + lane] = d * rsqrtf(var + 1e-5f) * g[lane] + bt[lane];
}

// ============================================================
// in_proj: (GTOT,32) @ (128,32)^T -> xm (first 64), z (last 64)
// ============================================================
__global__ __launch_bounds__(256) void gemm_inproj(
    const float* __restrict__ A, const float* __restrict__ Wm,
    float* __restrict__ oxm, float* __restrict__ oz)
{
    __shared__ float sA[64 * 33];
    __shared__ float sW[128 * 33];
    const int g0 = blockIdx.x * 64;
    const int tid = threadIdx.x;
    for (int i = tid; i < 64 * 32; i += 256) sA[(i >> 5) * 33 + (i & 31)] = A[g0 * 32 + i];
    for (int i = tid; i < 128 * 32; i += 256) sW[(i >> 5) * 33 + (i & 31)] = Wm[i];
    __syncthreads();
    for (int o = tid; o < 64 * 128; o += 256) {
        int r = o >> 7, c = o & 127;
        const float* a = &sA[r * 33];
        const float* w = &sW[c * 33];
        float s = 0.f;
#pragma unroll
        for (int k = 0; k < 32; k++) s = fmaf(a[k], w[k], s);
        int g = g0 + r;
        if (c < 64) oxm[g * 64 + c] = s;
        else        oz[g * 64 + (c - 64)] = s;
    }
}

// ============================================================
// causal depthwise conv1d (k=4) + silu
// ============================================================
__global__ __launch_bounds__(256) void conv1d_k(
    const float* __restrict__ xm, const float* __restrict__ wt,
    const float* __restrict__ bias, float* __restrict__ out)
{
    int idx = blockIdx.x * 256 + threadIdx.x;  // GTOT*64 threads
    int d = idx & 63;
    int g = idx >> 6;
    int l = g & (LSEQ - 1);
    float acc = bias[d];
#pragma unroll
    for (int k = 0; k < 4; k++) {
        int li = l - 3 + k;
        if (li >= 0) acc = fmaf(__ldg(&wt[d * 4 + k]), xm[(g - 3 + k) * 64 + d], acc);
    }
    out[idx] = acc / (1.f + expf(-acc));   // silu
}

// ============================================================
// x_proj: (GTOT,64) @ (66,64)^T -> dt(2), B(32), C(32)
// ============================================================
__global__ __launch_bounds__(256) void gemm_xproj(
    const float* __restrict__ A, const float* __restrict__ Wm,
    float* __restrict__ odt, float* __restrict__ oB, float* __restrict__ oC)
{
    __shared__ float sA[64 * 65];
    __shared__ float sW[66 * 65];
    const int g0 = blockIdx.x * 64;
    const int tid = threadIdx.x;
    for (int i = tid; i < 64 * 64; i += 256) sA[(i >> 6) * 65 + (i & 63)] = A[g0 * 64 + i];
    for (int i = tid; i < 66 * 64; i += 256) sW[(i >> 6) * 65 + (i & 63)] = Wm[i];
    __syncthreads();
    for (int o = tid; o < 64 * 66; o += 256) {
        int r = o / 66, c = o % 66;
        const float* a = &sA[r * 65];
        const float* w = &sW[c * 65];
        float s = 0.f;
#pragma unroll
        for (int k = 0; k < 64; k++) s = fmaf(a[k], w[k], s);
        int g = g0 + r;
        if (c < 2)        odt[g * 2 + c] = s;
        else if (c < 34)  oB[g * 32 + (c - 2)] = s;
        else              oC[g * 32 + (c - 34)] = s;
    }
}

// ============================================================
// prep: delta = softplus(dt @ dtW^T + dtb); pack float4 per (g,d)
// ============================================================
__global__ __launch_bounds__(256) void prep_k(
    const float* __restrict__ dt, const float* __restrict__ dtw,
    const float* __restrict__ dtb, const float* __restrict__ xm2,
    const float* __restrict__ z, const float* __restrict__ Dp,
    float4* __restrict__ P)
{
    int idx = blockIdx.x * 256 + threadIdx.x;
    int d = idx & 63;
    int g = idx >> 6;
    float t = dtb[d] + dt[g * 2] * dtw[d * 2] + dt[g * 2 + 1] * dtw[d * 2 + 1];
    float delta = (t > 20.f) ? t : log1pf(expf(t));
    float xv = xm2[idx];
    float zv = z[idx];
    P[idx] = make_float4(delta, delta * xv, xv * Dp[d], zv / (1.f + expf(-zv)));
}

// ============================================================
// selective scan: warp per (b,d), lane = state n
// ============================================================
__global__ __launch_bounds__(128) void scan_k(
    const float4* __restrict__ P, const float* __restrict__ Bm,
    const float* __restrict__ Cm, const float* __restrict__ Alog,
    float* __restrict__ ys)
{
    int warp = (blockIdx.x * blockDim.x + threadIdx.x) >> 5;
    int lane = threadIdx.x & 31;
    int b = warp >> 6, d = warp & 63;
    float a = -expf(Alog[d * 32 + lane]);
    float h = 0.f;
    long gbase = (long)b << 12;
    const float4* Pp = P + (gbase << 6) + d;
    const float*  Bp = Bm + (gbase << 5) + lane;
    const float*  Cp = Cm + (gbase << 5) + lane;
    float*        yp = ys + (gbase << 6) + d;
#pragma unroll 4
    for (int l = 0; l < LSEQ; l++) {
        float4 p = Pp[(long)l << 6];
        float bv = Bp[(long)l << 5];
        float cv = Cp[(long)l << 5];
        float dA = __expf(p.x * a);
        h = fmaf(h, dA, p.y * bv);
        float pr = h * cv;
#pragma unroll
        for (int o = 16; o; o >>= 1) pr += __shfl_xor_sync(0xffffffffu, pr, o);
        if (lane == 0) yp[(long)l << 6] = (pr + p.z) * p.w;
    }
}

// ============================================================
// out_proj: (GTOT,64) @ (32,64)^T, write transposed to (b,c,hw)
// ============================================================
__global__ __launch_bounds__(256) void gemm_outproj(
    const float* __restrict__ A, const float* __restrict__ Wm,
    float* __restrict__ oimg)
{
    __shared__ float sA[64 * 65];
    __shared__ float sW[32 * 65];
    const int g0 = blockIdx.x * 64;
    const int tid = threadIdx.x;
    for (int i = tid; i < 64 * 64; i += 256) sA[(i >> 6) * 65 + (i & 63)] = A[g0 * 64 + i];
    for (int i = tid; i < 32 * 64; i += 256) sW[(i >> 6) * 65 + (i & 63)] = Wm[i];
    __syncthreads();
    for (int o = tid; o < 64 * 32; o += 256) {
        int r = o >> 5, c = o & 31;
        const float* a = &sA[r * 65];
        const float* w = &sW[c * 65];
        float s = 0.f;
#pragma unroll
        for (int k = 0; k < 64; k++) s = fmaf(a[k], w[k], s);
        int g = g0 + r;
        int b = g >> 12, i = g & 4095;
        oimg[((long)(b * 32 + c) << 12) + i] = s;
    }
}

// ============================================================
extern "C" void kernel_launch(void* const* d_in, const int* in_sizes, int n_in,
                              void* d_out, int out_size)
{
    const float* x        = (const float*)d_in[0];
    const float* conv1_w  = (const float*)d_in[1];
    const float* conv1_b  = (const float*)d_in[2];
    const float* conv2_w  = (const float*)d_in[3];
    const float* conv2_b  = (const float*)d_in[4];
    const float* ln_g     = (const float*)d_in[5];
    const float* ln_b     = (const float*)d_in[6];
    const float* in_proj_w= (const float*)d_in[7];
    const float* conv1d_w = (const float*)d_in[8];
    const float* conv1d_b = (const float*)d_in[9];
    const float* x_proj_w = (const float*)d_in[10];
    const float* dt_proj_w= (const float*)d_in[11];
    const float* dt_proj_b= (const float*)d_in[12];
    const float* A_log    = (const float*)d_in[13];
    const float* Dp       = (const float*)d_in[14];
    const float* out_proj_w=(const float*)d_in[15];
    const float* smooth_w = (const float*)d_in[16];
    const float* smooth_b = (const float*)d_in[17];
    float* out = (float*)d_out;

    float  *t_, *x2_, *xs_, *xm_, *z_, *xm2_, *dt_, *B_, *C_, *ys_, *yimg_;
    float4 *P_;
    cudaGetSymbolAddress((void**)&t_,   g_t);
    cudaGetSymbolAddress((void**)&x2_,  g_x2);
    cudaGetSymbolAddress((void**)&xs_,  g_xs);
    cudaGetSymbolAddress((void**)&xm_,  g_xm);
    cudaGetSymbolAddress((void**)&z_,   g_z);
    cudaGetSymbolAddress((void**)&xm2_, g_xm2);
    cudaGetSymbolAddress((void**)&dt_,  g_dt);
    cudaGetSymbolAddress((void**)&B_,   g_Bm);
    cudaGetSymbolAddress((void**)&C_,   g_Cm);
    cudaGetSymbolAddress((void**)&P_,   g_P);
    cudaGetSymbolAddress((void**)&ys_,  g_ys);
    cudaGetSymbolAddress((void**)&yimg_,g_yimg);

    dim3 thr2d(16, 16);
    // 1. conv1 (32->64, relu)
    conv3x3_k<32, 64, true, false><<<dim3(2, 2, BATCH * 16), thr2d>>>(x, conv1_w, conv1_b, nullptr, t_);
    // 2. conv2 (64->32) + residual x
    conv3x3_k<64, 32, false, true><<<dim3(2, 2, BATCH * 8), thr2d>>>(t_, conv2_w, conv2_b, x, x2_);
    // 3. layernorm (groups of 32)
    ln_k<<<GTOT / 8, 256>>>(x2_, ln_g, ln_b, xs_);
    // 4. in_proj
    gemm_inproj<<<GTOT / 64, 256>>>(xs_, in_proj_w, xm_, z_);
    // 5. depthwise conv1d + silu
    conv1d_k<<<GTOT * 64 / 256, 256>>>(xm_, conv1d_w, conv1d_b, xm2_);
    // 6. x_proj
    gemm_xproj<<<GTOT / 64, 256>>>(xm2_, x_proj_w, dt_, B_, C_);
    // 7. prep (delta + packing)
    prep_k<<<GTOT * 64 / 256, 256>>>(dt_, dt_proj_w, dt_proj_b, xm2_, z_, Dp, P_);
    // 8. selective scan
    scan_k<<<64, 128>>>(P_, B_, C_, A_log, ys_);
    // 9. out_proj (writes transposed image layout)
    gemm_outproj<<<GTOT / 64, 256>>>(ys_, out_proj_w, yimg_);
    // 10. smooth conv (32->32)
    conv3x3_k<32, 32, false, false><<<dim3(2, 2, BATCH * 8), thr2d>>>(yimg_, smooth_w, smooth_b, nullptr, out);
}

// round 2
// speedup vs baseline: 2.8898x; 2.8898x over previous
#include <cuda_runtime.h>
#include <math.h>

// Problem constants
#define BATCH 4
#define C 32
#define H 64
#define W 64
#define HW 4096
#define LSEQ 4096
#define GTOT 16384
#define DIN 64
#define DST 32
#define DTR 2
#define CH 64          // number of chunks
#define LC 64          // chunk length

// -------- device scratch --------
__device__ float  g_t   [BATCH*64*HW];
__device__ float  g_x2  [BATCH*C*HW];
__device__ float  g_xs  [GTOT*C];
__device__ float  g_xm  [GTOT*DIN];
__device__ float  g_z   [GTOT*DIN];
__device__ float  g_xm2 [GTOT*DIN];
__device__ float  g_dt  [GTOT*DTR];
__device__ float  g_Bm  [GTOT*DST];
__device__ float  g_Cm  [GTOT*DST];
__device__ float4 g_P   [GTOT*DIN];      // {delta, delta*xm, xm*Dp, silu(z)}
__device__ float  g_ys  [GTOT*DIN];
__device__ float  g_yimg[BATCH*C*HW];
// chunked-scan state: layout [b][d][chunk][n]
__device__ float  g_cA   [BATCH*DIN*CH*DST];
__device__ float  g_cH   [BATCH*DIN*CH*DST];
__device__ float  g_hinit[BATCH*DIN*CH*DST];

// ============================================================
// 3x3 conv, pad 1, direct. 32x32 tile/block, 2x2 px * 4 oc per thread.
// ============================================================
template<int IC, int OC, bool RELU, bool RES>
__global__ __launch_bounds__(256) void conv3x3_k(
    const float* __restrict__ in, const float* __restrict__ wt,
    const float* __restrict__ bias, const float* __restrict__ res,
    float* __restrict__ out)
{
    __shared__ float tile[34][35];
    const int tx = threadIdx.x, ty = threadIdx.y;
    const int tid = ty * 16 + tx;
    const int zb = blockIdx.z;
    const int b   = zb / (OC / 4);
    const int oc0 = (zb % (OC / 4)) * 4;
    const int x0 = blockIdx.x * 32, y0 = blockIdx.y * 32;

    float acc[4][2][2];
#pragma unroll
    for (int j = 0; j < 4; j++) {
        float bv = bias[oc0 + j];
        acc[j][0][0] = bv; acc[j][0][1] = bv; acc[j][1][0] = bv; acc[j][1][1] = bv;
    }

    for (int ic = 0; ic < IC; ic++) {
        const float* ip = in + ((long)(b * IC + ic) << 12);
        __syncthreads();
        for (int i = tid; i < 34 * 34; i += 256) {
            int r = i / 34, c = i % 34;
            int yy = y0 + r - 1, xx = x0 + c - 1;
            float v = 0.f;
            if ((unsigned)yy < 64u && (unsigned)xx < 64u) v = ip[(yy << 6) + xx];
            tile[r][c] = v;
        }
        __syncthreads();
        float dr[4][4];
#pragma unroll
        for (int r = 0; r < 4; r++)
#pragma unroll
            for (int c = 0; c < 4; c++) dr[r][c] = tile[ty * 2 + r][tx * 2 + c];
#pragma unroll
        for (int j = 0; j < 4; j++) {
            const float* wp = wt + ((long)((oc0 + j) * IC + ic)) * 9;
#pragma unroll
            for (int ky = 0; ky < 3; ky++)
#pragma unroll
                for (int kx = 0; kx < 3; kx++) {
                    float wv = __ldg(wp + ky * 3 + kx);
#pragma unroll
                    for (int pr = 0; pr < 2; pr++)
#pragma unroll
                        for (int pc = 0; pc < 2; pc++)
                            acc[j][pr][pc] = fmaf(dr[pr + ky][pc + kx], wv, acc[j][pr][pc]);
                }
        }
    }

#pragma unroll
    for (int j = 0; j < 4; j++) {
        int oc = oc0 + j;
#pragma unroll
        for (int pr = 0; pr < 2; pr++)
#pragma unroll
            for (int pc = 0; pc < 2; pc++) {
                int y = y0 + ty * 2 + pr, x = x0 + tx * 2 + pc;
                float v = acc[j][pr][pc];
                if (RELU) v = fmaxf(v, 0.f);
                long off = ((long)(b * OC + oc) << 12) + (y << 6) + x;
                if (RES) v += res[off];
                out[off] = v;
            }
    }
}

// ============================================================
// LayerNorm over groups of 32 consecutive floats
// ============================================================
__global__ __launch_bounds__(256) void ln_k(
    const float* __restrict__ x, const float* __restrict__ g,
    const float* __restrict__ bt, float* __restrict__ out)
{
    int warp = (blockIdx.x * blockDim.x + threadIdx.x) >> 5;
    int lane = threadIdx.x & 31;
    if (warp >= GTOT) return;
    float v = x[warp * 32 + lane];
    float s = v;
#pragma unroll
    for (int o = 16; o; o >>= 1) s += __shfl_xor_sync(0xffffffffu, s, o);
    float mu = s * (1.f / 32.f);
    float d = v - mu;
    float q = d * d;
#pragma unroll
    for (int o = 16; o; o >>= 1) q += __shfl_xor_sync(0xffffffffu, q, o);
    float var = q * (1.f / 32.f);
    out[warp * 32 + lane] = d * rsqrtf(var + 1e-5f) * g[lane] + bt[lane];
}

// ============================================================
// in_proj: (GTOT,32) @ (128,32)^T -> xm (first 64), z (last 64)
// ============================================================
__global__ __launch_bounds__(256) void gemm_inproj(
    const float* __restrict__ A, const float* __restrict__ Wm,
    float* __restrict__ oxm, float* __restrict__ oz)
{
    __shared__ float sA[64 * 33];
    __shared__ float sW[128 * 33];
    const int g0 = blockIdx.x * 64;
    const int tid = threadIdx.x;
    for (int i = tid; i < 64 * 32; i += 256) sA[(i >> 5) * 33 + (i & 31)] = A[g0 * 32 + i];
    for (int i = tid; i < 128 * 32; i += 256) sW[(i >> 5) * 33 + (i & 31)] = Wm[i];
    __syncthreads();
    for (int o = tid; o < 64 * 128; o += 256) {
        int r = o >> 7, c = o & 127;
        const float* a = &sA[r * 33];
        const float* w = &sW[c * 33];
        float s = 0.f;
#pragma unroll
        for (int k = 0; k < 32; k++) s = fmaf(a[k], w[k], s);
        int g = g0 + r;
        if (c < 64) oxm[g * 64 + c] = s;
        else        oz[g * 64 + (c - 64)] = s;
    }
}

// ============================================================
// causal depthwise conv1d (k=4) + silu
// ============================================================
__global__ __launch_bounds__(256) void conv1d_k(
    const float* __restrict__ xm, const float* __restrict__ wt,
    const float* __restrict__ bias, float* __restrict__ out)
{
    int idx = blockIdx.x * 256 + threadIdx.x;
    int d = idx & 63;
    int g = idx >> 6;
    int l = g & (LSEQ - 1);
    float acc = bias[d];
#pragma unroll
    for (int k = 0; k < 4; k++) {
        int li = l - 3 + k;
        if (li >= 0) acc = fmaf(__ldg(&wt[d * 4 + k]), xm[(g - 3 + k) * 64 + d], acc);
    }
    out[idx] = acc / (1.f + expf(-acc));
}

// ============================================================
// x_proj: (GTOT,64) @ (66,64)^T -> dt(2), B(32), C(32)
// ============================================================
__global__ __launch_bounds__(256) void gemm_xproj(
    const float* __restrict__ A, const float* __restrict__ Wm,
    float* __restrict__ odt, float* __restrict__ oB, float* __restrict__ oC)
{
    __shared__ float sA[64 * 65];
    __shared__ float sW[66 * 65];
    const int g0 = blockIdx.x * 64;
    const int tid = threadIdx.x;
    for (int i = tid; i < 64 * 64; i += 256) sA[(i >> 6) * 65 + (i & 63)] = A[g0 * 64 + i];
    for (int i = tid; i < 66 * 64; i += 256) sW[(i >> 6) * 65 + (i & 63)] = Wm[i];
    __syncthreads();
    for (int o = tid; o < 64 * 66; o += 256) {
        int r = o / 66, c = o % 66;
        const float* a = &sA[r * 65];
        const float* w = &sW[c * 65];
        float s = 0.f;
#pragma unroll
        for (int k = 0; k < 64; k++) s = fmaf(a[k], w[k], s);
        int g = g0 + r;
        if (c < 2)        odt[g * 2 + c] = s;
        else if (c < 34)  oB[g * 32 + (c - 2)] = s;
        else              oC[g * 32 + (c - 34)] = s;
    }
}

// ============================================================
// prep: delta = softplus(dt @ dtW^T + dtb); pack float4 per (g,d)
// ============================================================
__global__ __launch_bounds__(256) void prep_k(
    const float* __restrict__ dt, const float* __restrict__ dtw,
    const float* __restrict__ dtb, const float* __restrict__ xm2,
    const float* __restrict__ z, const float* __restrict__ Dp,
    float4* __restrict__ P)
{
    int idx = blockIdx.x * 256 + threadIdx.x;
    int d = idx & 63;
    int g = idx >> 6;
    float t = dtb[d] + dt[g * 2] * dtw[d * 2] + dt[g * 2 + 1] * dtw[d * 2 + 1];
    float delta = (t > 20.f) ? t : log1pf(expf(t));
    float xv = xm2[idx];
    float zv = z[idx];
    P[idx] = make_float4(delta, delta * xv, xv * Dp[d], zv / (1.f + expf(-zv)));
}

// ============================================================
// chunked selective scan
// pass 1: warp per (b,d,chunk); local scan with h0=0; store prodA, hLocal
// ============================================================
__global__ __launch_bounds__(256) void scan1_k(
    const float4* __restrict__ P, const float* __restrict__ Bm,
    const float* __restrict__ Alog,
    float* __restrict__ cA, float* __restrict__ cH)
{
    int warp = (blockIdx.x * blockDim.x + threadIdx.x) >> 5;   // b*4096 + d*64 + ch
    int lane = threadIdx.x & 31;
    int ch = warp & (CH - 1);
    int d  = (warp >> 6) & (DIN - 1);
    int b  = warp >> 12;
    float a = -expf(Alog[d * 32 + lane]);
    long l0 = ((long)b << 12) + (long)ch * LC;
    const float2* Pp = (const float2*)(P + (l0 << 6) + d);   // read {delta, delta*x}
    const float*  Bp = Bm + (l0 << 5) + lane;
    float h = 0.f, ap = 1.f;
#pragma unroll 4
    for (int l = 0; l < LC; l++) {
        float2 p = Pp[l << 7];       // float2 index: 128 per row of 64 float4
        float bv = Bp[l << 5];
        float dA = __expf(p.x * a);
        ap *= dA;
        h = fmaf(h, dA, p.y * bv);
    }
    int idx = (warp << 5) + lane;
    cA[idx] = ap;
    cH[idx] = h;
}

// pass 2: warp per (b,d); sequential combine over chunks -> h_init per chunk
__global__ __launch_bounds__(256) void scan2_k(
    const float* __restrict__ cA, const float* __restrict__ cH,
    float* __restrict__ hinit)
{
    int warp = (blockIdx.x * blockDim.x + threadIdx.x) >> 5;   // b*64 + d, 256 warps
    int lane = threadIdx.x & 31;
    int base = warp << 11;    // *CH*DST
    float h = 0.f;
#pragma unroll 4
    for (int ch = 0; ch < CH; ch++) {
        int idx = base + (ch << 5) + lane;
        float ap = cA[idx];
        float hl = cH[idx];
        hinit[idx] = h;
        h = fmaf(h, ap, hl);
    }
}

// pass 3: warp per (b,d,chunk); rescan with true h_init, emit y
__global__ __launch_bounds__(256) void scan3_k(
    const float4* __restrict__ P, const float* __restrict__ Bm,
    const float* __restrict__ Cm, const float* __restrict__ Alog,
    const float* __restrict__ hinit, float* __restrict__ ys)
{
    int warp = (blockIdx.x * blockDim.x + threadIdx.x) >> 5;
    int lane = threadIdx.x & 31;
    int ch = warp & (CH - 1);
    int d  = (warp >> 6) & (DIN - 1);
    int b  = warp >> 12;
    float a = -expf(Alog[d * 32 + lane]);
    long l0 = ((long)b << 12) + (long)ch * LC;
    const float4* Pp = P + (l0 << 6) + d;
    const float*  Bp = Bm + (l0 << 5) + lane;
    const float*  Cp = Cm + (l0 << 5) + lane;
    float*        yp = ys + (l0 << 6) + d;
    float h = hinit[(warp << 5) + lane];
#pragma unroll 4
    for (int l = 0; l < LC; l++) {
        float4 p = Pp[l << 6];
        float bv = Bp[l << 5];
        float cv = Cp[l << 5];
        float dA = __expf(p.x * a);
        h = fmaf(h, dA, p.y * bv);
        float pr = h * cv;
#pragma unroll
        for (int o = 16; o; o >>= 1) pr += __shfl_xor_sync(0xffffffffu, pr, o);
        if (lane == 0) yp[l << 6] = (pr + p.z) * p.w;
    }
}

// ============================================================
// out_proj: (GTOT,64) @ (32,64)^T, write transposed to (b,c,hw)
// ============================================================
__global__ __launch_bounds__(256) void gemm_outproj(
    const float* __restrict__ A, const float* __restrict__ Wm,
    float* __restrict__ oimg)
{
    __shared__ float sA[64 * 65];
    __shared__ float sW[32 * 65];
    const int g0 = blockIdx.x * 64;
    const int tid = threadIdx.x;
    for (int i = tid; i < 64 * 64; i += 256) sA[(i >> 6) * 65 + (i & 63)] = A[g0 * 64 + i];
    for (int i = tid; i < 32 * 64; i += 256) sW[(i >> 6) * 65 + (i & 63)] = Wm[i];
    __syncthreads();
    for (int o = tid; o < 64 * 32; o += 256) {
        int r = o >> 5, c = o & 31;
        const float* a = &sA[r * 65];
        const float* w = &sW[c * 65];
        float s = 0.f;
#pragma unroll
        for (int k = 0; k < 64; k++) s = fmaf(a[k], w[k], s);
        int g = g0 + r;
        int b = g >> 12, i = g & 4095;
        oimg[((long)(b * 32 + c) << 12) + i] = s;
    }
}

// ============================================================
extern "C" void kernel_launch(void* const* d_in, const int* in_sizes, int n_in,
                              void* d_out, int out_size)
{
    const float* x        = (const float*)d_in[0];
    const float* conv1_w  = (const float*)d_in[1];
    const float* conv1_b  = (const float*)d_in[2];
    const float* conv2_w  = (const float*)d_in[3];
    const float* conv2_b  = (const float*)d_in[4];
    const float* ln_g     = (const float*)d_in[5];
    const float* ln_b     = (const float*)d_in[6];
    const float* in_proj_w= (const float*)d_in[7];
    const float* conv1d_w = (const float*)d_in[8];
    const float* conv1d_b = (const float*)d_in[9];
    const float* x_proj_w = (const float*)d_in[10];
    const float* dt_proj_w= (const float*)d_in[11];
    const float* dt_proj_b= (const float*)d_in[12];
    const float* A_log    = (const float*)d_in[13];
    const float* Dp       = (const float*)d_in[14];
    const float* out_proj_w=(const float*)d_in[15];
    const float* smooth_w = (const float*)d_in[16];
    const float* smooth_b = (const float*)d_in[17];
    float* out = (float*)d_out;

    float  *t_, *x2_, *xs_, *xm_, *z_, *xm2_, *dt_, *B_, *C_, *ys_, *yimg_;
    float  *cA_, *cH_, *hinit_;
    float4 *P_;
    cudaGetSymbolAddress((void**)&t_,   g_t);
    cudaGetSymbolAddress((void**)&x2_,  g_x2);
    cudaGetSymbolAddress((void**)&xs_,  g_xs);
    cudaGetSymbolAddress((void**)&xm_,  g_xm);
    cudaGetSymbolAddress((void**)&z_,   g_z);
    cudaGetSymbolAddress((void**)&xm2_, g_xm2);
    cudaGetSymbolAddress((void**)&dt_,  g_dt);
    cudaGetSymbolAddress((void**)&B_,   g_Bm);
    cudaGetSymbolAddress((void**)&C_,   g_Cm);
    cudaGetSymbolAddress((void**)&P_,   g_P);
    cudaGetSymbolAddress((void**)&ys_,  g_ys);
    cudaGetSymbolAddress((void**)&yimg_,g_yimg);
    cudaGetSymbolAddress((void**)&cA_,  g_cA);
    cudaGetSymbolAddress((void**)&cH_,  g_cH);
    cudaGetSymbolAddress((void**)&hinit_, g_hinit);

    dim3 thr2d(16, 16);
    conv3x3_k<32, 64, true, false><<<dim3(2, 2, BATCH * 16), thr2d>>>(x, conv1_w, conv1_b, nullptr, t_);
    conv3x3_k<64, 32, false, true><<<dim3(2, 2, BATCH * 8), thr2d>>>(t_, conv2_w, conv2_b, x, x2_);
    ln_k<<<GTOT / 8, 256>>>(x2_, ln_g, ln_b, xs_);
    gemm_inproj<<<GTOT / 64, 256>>>(xs_, in_proj_w, xm_, z_);
    conv1d_k<<<GTOT * 64 / 256, 256>>>(xm_, conv1d_w, conv1d_b, xm2_);
    gemm_xproj<<<GTOT / 64, 256>>>(xm2_, x_proj_w, dt_, B_, C_);
    prep_k<<<GTOT * 64 / 256, 256>>>(dt_, dt_proj_w, dt_proj_b, xm2_, z_, Dp, P_);
    // chunked scan: 16384 warps for pass1/3, 256 warps pass2
    scan1_k<<<BATCH * DIN * CH / 8, 256>>>(P_, B_, A_log, cA_, cH_);
    scan2_k<<<BATCH * DIN / 8, 256>>>(cA_, cH_, hinit_);
    scan3_k<<<BATCH * DIN * CH / 8, 256>>>(P_, B_, C_, A_log, hinit_, ys_);
    gemm_outproj<<<GTOT / 64, 256>>>(ys_, out_proj_w, yimg_);
    conv3x3_k<32, 32, false, false><<<dim3(2, 2, BATCH * 8), thr2d>>>(yimg_, smooth_w, smooth_b, nullptr, out);
}

// round 3
// speedup vs baseline: 2.9834x; 1.0324x over previous
#include <cuda_runtime.h>
#include <math.h>

#define BATCH 4
#define C 32
#define HW 4096
#define LSEQ 4096
#define GTOT 16384
#define DIN 64
#define DST 32
#define CH 64
#define LC 64

// -------- device scratch --------
__device__ float  g_t   [BATCH*64*HW];
__device__ float  g_x2  [BATCH*C*HW];
__device__ float  g_xm  [GTOT*DIN];
__device__ float  g_z   [GTOT*DIN];
__device__ float  g_Bm  [GTOT*DST];
__device__ float  g_Cm  [GTOT*DST];
__device__ float2 g_Pa  [GTOT*DIN];      // [b][d][l] {delta, delta*x}
__device__ float2 g_Pb  [GTOT*DIN];      // [b][d][l] {x*Dp, silu(z)}
__device__ float  g_ys  [GTOT*DIN];      // [b][d][l]
__device__ float  g_yimg[BATCH*C*HW];
__device__ float  g_cA   [BATCH*DIN*CH*DST];
__device__ float  g_cH   [BATCH*DIN*CH*DST];
__device__ float  g_hinit[BATCH*DIN*CH*DST];

// ============================================================
// 3x3 conv, pad 1, direct. 32x32 tile/block, 2x2 px * 4 oc per thread.
// ============================================================
template<int IC, int OC, bool RELU, bool RES>
__global__ __launch_bounds__(256) void conv3x3_k(
    const float* __restrict__ in, const float* __restrict__ wt,
    const float* __restrict__ bias, const float* __restrict__ res,
    float* __restrict__ out)
{
    __shared__ float tile[34][35];
    const int tx = threadIdx.x, ty = threadIdx.y;
    const int tid = ty * 16 + tx;
    const int zb = blockIdx.z;
    const int b   = zb / (OC / 4);
    const int oc0 = (zb % (OC / 4)) * 4;
    const int x0 = blockIdx.x * 32, y0 = blockIdx.y * 32;

    float acc[4][2][2];
#pragma unroll
    for (int j = 0; j < 4; j++) {
        float bv = bias[oc0 + j];
        acc[j][0][0] = bv; acc[j][0][1] = bv; acc[j][1][0] = bv; acc[j][1][1] = bv;
    }

    for (int ic = 0; ic < IC; ic++) {
        const float* ip = in + ((long)(b * IC + ic) << 12);
        __syncthreads();
        for (int i = tid; i < 34 * 34; i += 256) {
            int r = i / 34, c = i % 34;
            int yy = y0 + r - 1, xx = x0 + c - 1;
            float v = 0.f;
            if ((unsigned)yy < 64u && (unsigned)xx < 64u) v = ip[(yy << 6) + xx];
            tile[r][c] = v;
        }
        __syncthreads();
        float dr[4][4];
#pragma unroll
        for (int r = 0; r < 4; r++)
#pragma unroll
            for (int c = 0; c < 4; c++) dr[r][c] = tile[ty * 2 + r][tx * 2 + c];
#pragma unroll
        for (int j = 0; j < 4; j++) {
            const float* wp = wt + ((long)((oc0 + j) * IC + ic)) * 9;
#pragma unroll
            for (int ky = 0; ky < 3; ky++)
#pragma unroll
                for (int kx = 0; kx < 3; kx++) {
                    float wv = __ldg(wp + ky * 3 + kx);
#pragma unroll
                    for (int pr = 0; pr < 2; pr++)
#pragma unroll
                        for (int pc = 0; pc < 2; pc++)
                            acc[j][pr][pc] = fmaf(dr[pr + ky][pc + kx], wv, acc[j][pr][pc]);
                }
        }
    }

#pragma unroll
    for (int j = 0; j < 4; j++) {
        int oc = oc0 + j;
#pragma unroll
        for (int pr = 0; pr < 2; pr++)
#pragma unroll
            for (int pc = 0; pc < 2; pc++) {
                int y = y0 + ty * 2 + pr, x = x0 + tx * 2 + pc;
                float v = acc[j][pr][pc];
                if (RELU) v = fmaxf(v, 0.f);
                long off = ((long)(b * OC + oc) << 12) + (y << 6) + x;
                if (RES) v += res[off];
                out[off] = v;
            }
    }
}

// ============================================================
// fused LayerNorm + in_proj: 64 rows/block, K=32, N=128
// ============================================================
__global__ __launch_bounds__(256) void inproj_k(
    const float* __restrict__ x2, const float* __restrict__ lg,
    const float* __restrict__ lb, const float* __restrict__ Wm,
    float* __restrict__ xm, float* __restrict__ z)
{
    __shared__ float sA[64 * 36];
    __shared__ float sW[128 * 36];
    const int g0 = blockIdx.x * 64;
    const int tid = threadIdx.x;
    const int warp = tid >> 5, lane = tid & 31;

    for (int i = tid; i < 128 * 32; i += 256) sW[(i >> 5) * 36 + (i & 31)] = Wm[i];
    // LN staging: warp per row
    for (int rr = warp; rr < 64; rr += 8) {
        float v = x2[(g0 + rr) * 32 + lane];
        float s = v;
#pragma unroll
        for (int o = 16; o; o >>= 1) s += __shfl_xor_sync(0xffffffffu, s, o);
        float mu = s * (1.f / 32.f);
        float d = v - mu;
        float q = d * d;
#pragma unroll
        for (int o = 16; o; o >>= 1) q += __shfl_xor_sync(0xffffffffu, q, o);
        sA[rr * 36 + lane] = d * rsqrtf(q * (1.f / 32.f) + 1e-5f) * lg[lane] + lb[lane];
    }
    __syncthreads();

    const int rg = tid & 15, cg = tid >> 4;
    const int r0 = rg * 4, c0 = cg * 8;
    float acc[4][8];
#pragma unroll
    for (int j = 0; j < 4; j++)
#pragma unroll
        for (int i = 0; i < 8; i++) acc[j][i] = 0.f;

#pragma unroll
    for (int k0 = 0; k0 < 32; k0 += 4) {
        float4 a4[4], w4[8];
#pragma unroll
        for (int j = 0; j < 4; j++) a4[j] = *(const float4*)&sA[(r0 + j) * 36 + k0];
#pragma unroll
        for (int i = 0; i < 8; i++) w4[i] = *(const float4*)&sW[(c0 + i) * 36 + k0];
#pragma unroll
        for (int j = 0; j < 4; j++)
#pragma unroll
            for (int i = 0; i < 8; i++) {
                acc[j][i] = fmaf(a4[j].x, w4[i].x, acc[j][i]);
                acc[j][i] = fmaf(a4[j].y, w4[i].y, acc[j][i]);
                acc[j][i] = fmaf(a4[j].z, w4[i].z, acc[j][i]);
                acc[j][i] = fmaf(a4[j].w, w4[i].w, acc[j][i]);
            }
    }
#pragma unroll
    for (int j = 0; j < 4; j++) {
        int g = g0 + r0 + j;
        float4 v0 = make_float4(acc[j][0], acc[j][1], acc[j][2], acc[j][3]);
        float4 v1 = make_float4(acc[j][4], acc[j][5], acc[j][6], acc[j][7]);
        if (cg < 8) {
            *(float4*)&xm[g * 64 + c0]     = v0;
            *(float4*)&xm[g * 64 + c0 + 4] = v1;
        } else {
            *(float4*)&z[g * 64 + c0 - 64]     = v0;
            *(float4*)&z[g * 64 + c0 - 64 + 4] = v1;
        }
    }
}

// ============================================================
// mid_k: conv1d+silu + x_proj GEMM + dt_proj/softplus + P packing
// dynamic smem layout (floats):
//   sxm2 [0,4352)  64x68
//   sW   [4352,8576)  66x64
//   sz   [8576,12736) 64x65
//   sdt  [12736,12864)
// ============================================================
#define MID_SMEM_FLOATS 12864
__global__ __launch_bounds__(256) void mid_k(
    const float* __restrict__ xm, const float* __restrict__ z,
    const float* __restrict__ w1, const float* __restrict__ b1,
    const float* __restrict__ xw,
    const float* __restrict__ dtw, const float* __restrict__ dtb,
    const float* __restrict__ Dp,
    float* __restrict__ Bm, float* __restrict__ Cm,
    float2* __restrict__ Pa, float2* __restrict__ Pb)
{
    extern __shared__ float sm[];
    float* sxm2 = sm;
    float* sW   = sm + 4352;
    float* sz   = sm + 8576;
    float* sdt  = sm + 12736;
    const int g0 = blockIdx.x * 64;
    const int tid = threadIdx.x;
    const int B0 = g0 & ~4095;

    // conv1d + silu (reads xm from global, heavy L1 reuse), stage z
    for (int i = tid; i < 64 * 64; i += 256) {
        int d = i & 63, r = i >> 6;
        float acc = __ldg(&b1[d]);
#pragma unroll
        for (int k = 0; k < 4; k++) {
            int gl = g0 + r - 3 + k;
            float v = (gl >= B0) ? xm[gl * 64 + d] : 0.f;
            acc = fmaf(__ldg(&w1[d * 4 + k]), v, acc);
        }
        sxm2[r * 68 + d] = acc / (1.f + __expf(-acc));
        sz[r * 65 + d] = z[(g0 + r) * 64 + d];
    }
    for (int i = tid; i < 66 * 16; i += 256)
        ((float4*)sW)[i] = ((const float4*)xw)[i];
    __syncthreads();

    // GEMM: (64x64) @ (66x64)^T, threads 0..143, tile 4x8
    if (tid < 144) {
        const int rg = tid % 16, cg = tid / 16;
        const int r0 = rg * 4, c0 = cg * 8;
        float acc[4][8];
#pragma unroll
        for (int j = 0; j < 4; j++)
#pragma unroll
            for (int i = 0; i < 8; i++) acc[j][i] = 0.f;
#pragma unroll 4
        for (int k0 = 0; k0 < 64; k0 += 4) {
            float4 a4[4], w4[8];
#pragma unroll
            for (int j = 0; j < 4; j++) a4[j] = *(const float4*)&sxm2[(r0 + j) * 68 + k0];
#pragma unroll
            for (int i = 0; i < 8; i++) {
                int c = c0 + i; if (c > 65) c = 65;
                w4[i] = *(const float4*)&sW[c * 64 + k0];
            }
#pragma unroll
            for (int j = 0; j < 4; j++)
#pragma unroll
                for (int i = 0; i < 8; i++) {
                    acc[j][i] = fmaf(a4[j].x, w4[i].x, acc[j][i]);
                    acc[j][i] = fmaf(a4[j].y, w4[i].y, acc[j][i]);
                    acc[j][i] = fmaf(a4[j].z, w4[i].z, acc[j][i]);
                    acc[j][i] = fmaf(a4[j].w, w4[i].w, acc[j][i]);
                }
        }
#pragma unroll
        for (int j = 0; j < 4; j++) {
            int r = r0 + j, g = g0 + r;
#pragma unroll
            for (int i = 0; i < 8; i++) {
                int c = c0 + i;
                float v = acc[j][i];
                if (c < 2)       sdt[r * 2 + c] = v;
                else if (c < 34) Bm[g * 32 + c - 2] = v;
                else if (c < 66) Cm[g * 32 + c - 34] = v;
            }
        }
    }
    __syncthreads();

    // epilogue: delta + P packing (P layout [b][d][l])
    const int b = g0 >> 12;
    const int lb = g0 & 4095;
    const int l = tid & 63, dg = tid >> 6;
    const float dt0 = sdt[l * 2], dt1 = sdt[l * 2 + 1];
#pragma unroll
    for (int j = 0; j < 16; j++) {
        int d = dg * 16 + j;
        float t = fmaf(dt0, __ldg(&dtw[d * 2]), fmaf(dt1, __ldg(&dtw[d * 2 + 1]), __ldg(&dtb[d])));
        float delta = (t > 20.f) ? t : log1pf(__expf(t));
        float xv = sxm2[l * 68 + d];
        float zv = sz[l * 65 + d];
        long pbase = ((long)(b * 64 + d) << 12) + lb + l;
        Pa[pbase] = make_float2(delta, delta * xv);
        Pb[pbase] = make_float2(xv * __ldg(&Dp[d]), zv / (1.f + __expf(-zv)));
    }
}

// ============================================================
// chunked scan pass 1
// ============================================================
__global__ __launch_bounds__(256) void scan1_k(
    const float2* __restrict__ Pa, const float* __restrict__ Bm,
    const float* __restrict__ Alog,
    float* __restrict__ cA, float* __restrict__ cH)
{
    int warp = (blockIdx.x * blockDim.x + threadIdx.x) >> 5;
    int lane = threadIdx.x & 31;
    int ch = warp & (CH - 1);
    int d  = (warp >> 6) & (DIN - 1);
    int b  = warp >> 12;
    float a = -expf(Alog[d * 32 + lane]);
    const float2* Pp = Pa + ((long)(b * 64 + d) << 12) + ch * LC;
    const float*  Bp = Bm + ((long)((b << 12) + ch * LC) << 5) + lane;
    float h = 0.f, ap = 1.f;
#pragma unroll 8
    for (int l = 0; l < LC; l++) {
        float2 p = Pp[l];
        float bv = Bp[l << 5];
        float dA = __expf(p.x * a);
        ap *= dA;
        h = fmaf(h, dA, p.y * bv);
    }
    int idx = (warp << 5) + lane;
    cA[idx] = ap;
    cH[idx] = h;
}

// pass 2: sequential combine over chunks
__global__ __launch_bounds__(256) void scan2_k(
    const float* __restrict__ cA, const float* __restrict__ cH,
    float* __restrict__ hinit)
{
    int warp = (blockIdx.x * blockDim.x + threadIdx.x) >> 5;
    int lane = threadIdx.x & 31;
    int base = warp << 11;
    float h = 0.f;
#pragma unroll 4
    for (int ch = 0; ch < CH; ch++) {
        int idx = base + (ch << 5) + lane;
        float ap = cA[idx];
        float hl = cH[idx];
        hinit[idx] = h;
        h = fmaf(h, ap, hl);
    }
}

// pass 3: rescan with true h_init, emit y (register-staged coalesced stores)
__global__ __launch_bounds__(256) void scan3_k(
    const float2* __restrict__ Pa, const float2* __restrict__ Pb,
    const float* __restrict__ Bm, const float* __restrict__ Cm,
    const float* __restrict__ Alog, const float* __restrict__ hinit,
    float* __restrict__ ys)
{
    int warp = (blockIdx.x * blockDim.x + threadIdx.x) >> 5;
    int lane = threadIdx.x & 31;
    int ch = warp & (CH - 1);
    int d  = (warp >> 6) & (DIN - 1);
    int b  = warp >> 12;
    float a = -expf(Alog[d * 32 + lane]);
    long pbase = ((long)(b * 64 + d) << 12) + ch * LC;
    const float2* PaP = Pa + pbase;
    const float2* PbP = Pb + pbase;
    const float*  Bp = Bm + ((long)((b << 12) + ch * LC) << 5) + lane;
    const float*  Cp = Cm + ((long)((b << 12) + ch * LC) << 5) + lane;
    float h = hinit[(warp << 5) + lane];
#pragma unroll
    for (int half = 0; half < 2; half++) {
        float yv = 0.f;
#pragma unroll
        for (int j = 0; j < 32; j++) {
            int l = half * 32 + j;
            float2 pa = PaP[l];
            float bv = Bp[l << 5];
            float cv = Cp[l << 5];
            float dA = __expf(pa.x * a);
            h = fmaf(h, dA, pa.y * bv);
            float pr = h * cv;
#pragma unroll
            for (int o = 16; o; o >>= 1) pr += __shfl_xor_sync(0xffffffffu, pr, o);
            float2 pb = PbP[l];
            float val = (pr + pb.x) * pb.y;
            if (lane == j) yv = val;
        }
        ys[pbase + half * 32 + lane] = yv;
    }
}

// ============================================================
// out_proj: reads ys [b][d][l], writes yimg (b,c,hw)
// ============================================================
__global__ __launch_bounds__(256) void outproj_k(
    const float* __restrict__ ys, const float* __restrict__ Wo,
    float* __restrict__ oimg)
{
    __shared__ float sA[64 * 68];
    __shared__ float sW[32 * 68];
    const int g0 = blockIdx.x * 64;
    const int tid = threadIdx.x;
    const int b = g0 >> 12;
    const int lb = g0 & 4095;

    for (int i = tid; i < 64 * 64; i += 256) {
        int d = i >> 6, l = i & 63;
        sA[l * 68 + d] = ys[((long)(b * 64 + d) << 12) + lb + l];
    }
    for (int i = tid; i < 32 * 64; i += 256) {
        int c = i >> 6, k = i & 63;
        sW[c * 68 + k] = Wo[i];
    }
    __syncthreads();

    const int rg = tid & 31, cg = tid >> 5;
    const int r0 = rg * 2, c0 = cg * 4;
    float acc[2][4];
#pragma unroll
    for (int j = 0; j < 2; j++)
#pragma unroll
        for (int i = 0; i < 4; i++) acc[j][i] = 0.f;
#pragma unroll 4
    for (int k0 = 0; k0 < 64; k0 += 4) {
        float4 a4[2], w4[4];
#pragma unroll
        for (int j = 0; j < 2; j++) a4[j] = *(const float4*)&sA[(r0 + j) * 68 + k0];
#pragma unroll
        for (int i = 0; i < 4; i++) w4[i] = *(const float4*)&sW[(c0 + i) * 68 + k0];
#pragma unroll
        for (int j = 0; j < 2; j++)
#pragma unroll
            for (int i = 0; i < 4; i++) {
                acc[j][i] = fmaf(a4[j].x, w4[i].x, acc[j][i]);
                acc[j][i] = fmaf(a4[j].y, w4[i].y, acc[j][i]);
                acc[j][i] = fmaf(a4[j].z, w4[i].z, acc[j][i]);
                acc[j][i] = fmaf(a4[j].w, w4[i].w, acc[j][i]);
            }
    }
#pragma unroll
    for (int i = 0; i < 4; i++) {
        int c = c0 + i;
#pragma unroll
        for (int j = 0; j < 2; j++)
            oimg[((long)(b * 32 + c) << 12) + lb + r0 + j] = acc[j][i];
    }
}

// ============================================================
extern "C" void kernel_launch(void* const* d_in, const int* in_sizes, int n_in,
                              void* d_out, int out_size)
{
    const float* x        = (const float*)d_in[0];
    const float* conv1_w  = (const float*)d_in[1];
    const float* conv1_b  = (const float*)d_in[2];
    const float* conv2_w  = (const float*)d_in[3];
    const float* conv2_b  = (const float*)d_in[4];
    const float* ln_g     = (const float*)d_in[5];
    const float* ln_b     = (const float*)d_in[6];
    const float* in_proj_w= (const float*)d_in[7];
    const float* conv1d_w = (const float*)d_in[8];
    const float* conv1d_b = (const float*)d_in[9];
    const float* x_proj_w = (const float*)d_in[10];
    const float* dt_proj_w= (const float*)d_in[11];
    const float* dt_proj_b= (const float*)d_in[12];
    const float* A_log    = (const float*)d_in[13];
    const float* Dp       = (const float*)d_in[14];
    const float* out_proj_w=(const float*)d_in[15];
    const float* smooth_w = (const float*)d_in[16];
    const float* smooth_b = (const float*)d_in[17];
    float* out = (float*)d_out;

    float  *t_, *x2_, *xm_, *z_, *B_, *C_, *ys_, *yimg_, *cA_, *cH_, *hinit_;
    float2 *Pa_, *Pb_;
    cudaGetSymbolAddress((void**)&t_,   g_t);
    cudaGetSymbolAddress((void**)&x2_,  g_x2);
    cudaGetSymbolAddress((void**)&xm_,  g_xm);
    cudaGetSymbolAddress((void**)&z_,   g_z);
    cudaGetSymbolAddress((void**)&B_,   g_Bm);
    cudaGetSymbolAddress((void**)&C_,   g_Cm);
    cudaGetSymbolAddress((void**)&Pa_,  g_Pa);
    cudaGetSymbolAddress((void**)&Pb_,  g_Pb);
    cudaGetSymbolAddress((void**)&ys_,  g_ys);
    cudaGetSymbolAddress((void**)&yimg_,g_yimg);
    cudaGetSymbolAddress((void**)&cA_,  g_cA);
    cudaGetSymbolAddress((void**)&cH_,  g_cH);
    cudaGetSymbolAddress((void**)&hinit_, g_hinit);

    cudaFuncSetAttribute(mid_k, cudaFuncAttributeMaxDynamicSharedMemorySize,
                         MID_SMEM_FLOATS * 4);

    dim3 thr2d(16, 16);
    conv3x3_k<32, 64, true, false><<<dim3(2, 2, BATCH * 16), thr2d>>>(x, conv1_w, conv1_b, nullptr, t_);
    conv3x3_k<64, 32, false, true><<<dim3(2, 2, BATCH * 8), thr2d>>>(t_, conv2_w, conv2_b, x, x2_);
    inproj_k<<<GTOT / 64, 256>>>(x2_, ln_g, ln_b, in_proj_w, xm_, z_);
    mid_k<<<GTOT / 64, 256, MID_SMEM_FLOATS * 4>>>(xm_, z_, conv1d_w, conv1d_b,
        x_proj_w, dt_proj_w, dt_proj_b, Dp, B_, C_, Pa_, Pb_);
    scan1_k<<<BATCH * DIN * CH / 8, 256>>>(Pa_, B_, A_log, cA_, cH_);
    scan2_k<<<BATCH * DIN / 8, 256>>>(cA_, cH_, hinit_);
    scan3_k<<<BATCH * DIN * CH / 8, 256>>>(Pa_, Pb_, B_, C_, A_log, hinit_, ys_);
    outproj_k<<<GTOT / 64, 256>>>(ys_, out_proj_w, yimg_);
    conv3x3_k<32, 32, false, false><<<dim3(2, 2, BATCH * 8), thr2d>>>(yimg_, smooth_w, smooth_b, nullptr, out);
}

// round 5
// speedup vs baseline: 5.2996x; 1.7763x over previous
#include <cuda_runtime.h>
#include <math.h>

#define BATCH 4
#define C 32
#define HW 4096
#define LSEQ 4096
#define GTOT 16384
#define DIN 64
#define DST 32
#define CH 64
#define LC 64

// -------- device scratch --------
__device__ float  g_t   [BATCH*64*HW];
__device__ float  g_x2  [BATCH*C*HW];
__device__ float  g_xm  [GTOT*DIN];
__device__ float  g_z   [GTOT*DIN];
__device__ float  g_Bm  [GTOT*DST];
__device__ float  g_Cm  [GTOT*DST];
__device__ float2 g_Pa  [GTOT*DIN];      // [b][d][l] {r=exp(-delta), delta*x}
__device__ float2 g_Pb  [GTOT*DIN];      // [b][d][l] {x*Dp, silu(z)}
__device__ float  g_ys  [GTOT*DIN];      // [b][d][l]
__device__ float  g_yimg[BATCH*C*HW];
__device__ float  g_cA   [BATCH*DIN*CH*DST];
__device__ float  g_cH   [BATCH*DIN*CH*DST];
__device__ float  g_hinit[BATCH*DIN*CH*DST];

// warp sum: shuffle butterfly (redux.f32 not supported on sm_103)
__device__ __forceinline__ float warp_sum(float v) {
#pragma unroll
    for (int o = 16; o; o >>= 1) v += __shfl_xor_sync(0xffffffffu, v, o);
    return v;
}

// r^e for e in [1,63], ~10 ops, no MUFU
__device__ __forceinline__ float rpow(float r, int e) {
    float q = (e & 1) ? r : 1.0f;
    float s = r * r;
    q = (e & 2)  ? q * s : q; s *= s;
    q = (e & 4)  ? q * s : q; s *= s;
    q = (e & 8)  ? q * s : q; s *= s;
    q = (e & 16) ? q * s : q; s *= s;
    q = (e & 32) ? q * s : q;
    return q;
}

// ============================================================
// 3x3 conv, pad 1, direct. 32x32 tile/block, OCG oc per thread.
// Weights in smem, input tile double-buffered.
// ============================================================
template<int IC, int OC, int OCG, bool RELU, bool RES>
__global__ __launch_bounds__(256) void conv3x3_k(
    const float* __restrict__ in, const float* __restrict__ wt,
    const float* __restrict__ bias, const float* __restrict__ res,
    float* __restrict__ out)
{
    __shared__ float tile[2][34 * 35];
    __shared__ float sWt[OCG * IC * 9];
    const int tx = threadIdx.x, ty = threadIdx.y;
    const int tid = ty * 16 + tx;
    const int zb = blockIdx.z;
    const int b   = zb / (OC / OCG);
    const int oc0 = (zb % (OC / OCG)) * OCG;
    const int x0 = blockIdx.x * 32, y0 = blockIdx.y * 32;

    for (int i = tid; i < OCG * IC * 9; i += 256) sWt[i] = wt[oc0 * IC * 9 + i];

    int  off[5], si[5];
    bool vd[5], inb[5];
#pragma unroll
    for (int k = 0; k < 5; k++) {
        int i = tid + k * 256;
        inb[k] = i < 1156;
        int r = i / 34, c = i % 34;
        int yy = y0 + r - 1, xx = x0 + c - 1;
        vd[k] = inb[k] && (unsigned)yy < 64u && (unsigned)xx < 64u;
        off[k] = (yy << 6) + xx;
        si[k] = r * 35 + c;
    }

    float acc[OCG][2][2];
#pragma unroll
    for (int j = 0; j < OCG; j++) {
        float bv = bias[oc0 + j];
#pragma unroll
        for (int pr = 0; pr < 2; pr++)
#pragma unroll
            for (int pc = 0; pc < 2; pc++) acc[j][pr][pc] = bv;
    }

    const float* ip0 = in + ((long)(b * IC) << 12);
#pragma unroll
    for (int k = 0; k < 5; k++)
        if (inb[k]) tile[0][si[k]] = vd[k] ? ip0[off[k]] : 0.f;
    __syncthreads();

    for (int ic = 0; ic < IC; ic++) {
        float pf[5];
        if (ic + 1 < IC) {
            const float* ipn = ip0 + ((long)(ic + 1) << 12);
#pragma unroll
            for (int k = 0; k < 5; k++) pf[k] = vd[k] ? ipn[off[k]] : 0.f;
        }
        const float* tb = tile[ic & 1];
        float dr[4][4];
#pragma unroll
        for (int r = 0; r < 4; r++)
#pragma unroll
            for (int c = 0; c < 4; c++) dr[r][c] = tb[(ty * 2 + r) * 35 + tx * 2 + c];
#pragma unroll
        for (int j = 0; j < OCG; j++) {
            const float* wp = sWt + (j * IC + ic) * 9;
#pragma unroll
            for (int ky = 0; ky < 3; ky++)
#pragma unroll
                for (int kx = 0; kx < 3; kx++) {
                    float wv = wp[ky * 3 + kx];
#pragma unroll
                    for (int pr = 0; pr < 2; pr++)
#pragma unroll
                        for (int pc = 0; pc < 2; pc++)
                            acc[j][pr][pc] = fmaf(dr[pr + ky][pc + kx], wv, acc[j][pr][pc]);
                }
        }
        if (ic + 1 < IC) {
            float* tn = tile[(ic + 1) & 1];
#pragma unroll
            for (int k = 0; k < 5; k++)
                if (inb[k]) tn[si[k]] = pf[k];
            __syncthreads();
        }
    }

#pragma unroll
    for (int j = 0; j < OCG; j++) {
        int oc = oc0 + j;
#pragma unroll
        for (int pr = 0; pr < 2; pr++)
#pragma unroll
            for (int pc = 0; pc < 2; pc++) {
                int y = y0 + ty * 2 + pr, x = x0 + tx * 2 + pc;
                float v = acc[j][pr][pc];
                if (RELU) v = fmaxf(v, 0.f);
                long o = ((long)(b * OC + oc) << 12) + (y << 6) + x;
                if (RES) v += res[o];
                out[o] = v;
            }
    }
}

// ============================================================
// fused LayerNorm + in_proj: 64 rows/block, K=32, N=128
// ============================================================
__global__ __launch_bounds__(256) void inproj_k(
    const float* __restrict__ x2, const float* __restrict__ lg,
    const float* __restrict__ lb, const float* __restrict__ Wm,
    float* __restrict__ xm, float* __restrict__ z)
{
    __shared__ float sA[64 * 36];
    __shared__ float sW[128 * 36];
    const int g0 = blockIdx.x * 64;
    const int tid = threadIdx.x;
    const int warp = tid >> 5, lane = tid & 31;

    for (int i = tid; i < 128 * 32; i += 256) sW[(i >> 5) * 36 + (i & 31)] = Wm[i];
    for (int rr = warp; rr < 64; rr += 8) {
        float v = x2[(g0 + rr) * 32 + lane];
        float s = warp_sum(v);
        float mu = s * (1.f / 32.f);
        float d = v - mu;
        float q = warp_sum(d * d);
        sA[rr * 36 + lane] = d * rsqrtf(q * (1.f / 32.f) + 1e-5f) * lg[lane] + lb[lane];
    }
    __syncthreads();

    const int rg = tid & 15, cg = tid >> 4;
    const int r0 = rg * 4, c0 = cg * 8;
    float acc[4][8];
#pragma unroll
    for (int j = 0; j < 4; j++)
#pragma unroll
        for (int i = 0; i < 8; i++) acc[j][i] = 0.f;

#pragma unroll
    for (int k0 = 0; k0 < 32; k0 += 4) {
        float4 a4[4], w4[8];
#pragma unroll
        for (int j = 0; j < 4; j++) a4[j] = *(const float4*)&sA[(r0 + j) * 36 + k0];
#pragma unroll
        for (int i = 0; i < 8; i++) w4[i] = *(const float4*)&sW[(c0 + i) * 36 + k0];
#pragma unroll
        for (int j = 0; j < 4; j++)
#pragma unroll
            for (int i = 0; i < 8; i++) {
                acc[j][i] = fmaf(a4[j].x, w4[i].x, acc[j][i]);
                acc[j][i] = fmaf(a4[j].y, w4[i].y, acc[j][i]);
                acc[j][i] = fmaf(a4[j].z, w4[i].z, acc[j][i]);
                acc[j][i] = fmaf(a4[j].w, w4[i].w, acc[j][i]);
            }
    }
#pragma unroll
    for (int j = 0; j < 4; j++) {
        int g = g0 + r0 + j;
        float4 v0 = make_float4(acc[j][0], acc[j][1], acc[j][2], acc[j][3]);
        float4 v1 = make_float4(acc[j][4], acc[j][5], acc[j][6], acc[j][7]);
        if (cg < 8) {
            *(float4*)&xm[g * 64 + c0]     = v0;
            *(float4*)&xm[g * 64 + c0 + 4] = v1;
        } else {
            *(float4*)&z[g * 64 + c0 - 64]     = v0;
            *(float4*)&z[g * 64 + c0 - 64 + 4] = v1;
        }
    }
}

// ============================================================
// mid_k: conv1d+silu + x_proj GEMM + dt_proj/softplus + P packing
// ============================================================
#define MID_SMEM_FLOATS 12864
__global__ __launch_bounds__(256) void mid_k(
    const float* __restrict__ xm, const float* __restrict__ z,
    const float* __restrict__ w1, const float* __restrict__ b1,
    const float* __restrict__ xw,
    const float* __restrict__ dtw, const float* __restrict__ dtb,
    const float* __restrict__ Dp,
    float* __restrict__ Bm, float* __restrict__ Cm,
    float2* __restrict__ Pa, float2* __restrict__ Pb)
{
    extern __shared__ float sm[];
    float* sxm2 = sm;
    float* sW   = sm + 4352;
    float* sz   = sm + 8576;
    float* sdt  = sm + 12736;
    const int g0 = blockIdx.x * 64;
    const int tid = threadIdx.x;
    const int B0 = g0 & ~4095;

    for (int i = tid; i < 64 * 64; i += 256) {
        int d = i & 63, r = i >> 6;
        float acc = __ldg(&b1[d]);
#pragma unroll
        for (int k = 0; k < 4; k++) {
            int gl = g0 + r - 3 + k;
            float v = (gl >= B0) ? xm[gl * 64 + d] : 0.f;
            acc = fmaf(__ldg(&w1[d * 4 + k]), v, acc);
        }
        sxm2[r * 68 + d] = acc / (1.f + __expf(-acc));
        sz[r * 65 + d] = z[(g0 + r) * 64 + d];
    }
    for (int i = tid; i < 66 * 16; i += 256)
        ((float4*)sW)[i] = ((const float4*)xw)[i];
    __syncthreads();

    if (tid < 144) {
        const int rg = tid % 16, cg = tid / 16;
        const int r0 = rg * 4, c0 = cg * 8;
        float acc[4][8];
#pragma unroll
        for (int j = 0; j < 4; j++)
#pragma unroll
            for (int i = 0; i < 8; i++) acc[j][i] = 0.f;
#pragma unroll 4
        for (int k0 = 0; k0 < 64; k0 += 4) {
            float4 a4[4], w4[8];
#pragma unroll
            for (int j = 0; j < 4; j++) a4[j] = *(const float4*)&sxm2[(r0 + j) * 68 + k0];
#pragma unroll
            for (int i = 0; i < 8; i++) {
                int c = c0 + i; if (c > 65) c = 65;
                w4[i] = *(const float4*)&sW[c * 64 + k0];
            }
#pragma unroll
            for (int j = 0; j < 4; j++)
#pragma unroll
                for (int i = 0; i < 8; i++) {
                    acc[j][i] = fmaf(a4[j].x, w4[i].x, acc[j][i]);
                    acc[j][i] = fmaf(a4[j].y, w4[i].y, acc[j][i]);
                    acc[j][i] = fmaf(a4[j].z, w4[i].z, acc[j][i]);
                    acc[j][i] = fmaf(a4[j].w, w4[i].w, acc[j][i]);
                }
        }
#pragma unroll
        for (int j = 0; j < 4; j++) {
            int r = r0 + j, g = g0 + r;
#pragma unroll
            for (int i = 0; i < 8; i++) {
                int c = c0 + i;
                float v = acc[j][i];
                if (c < 2)       sdt[r * 2 + c] = v;
                else if (c < 34) Bm[g * 32 + c - 2] = v;
                else if (c < 66) Cm[g * 32 + c - 34] = v;
            }
        }
    }
    __syncthreads();

    const int b = g0 >> 12;
    const int lb = g0 & 4095;
    const int l = tid & 63, dg = tid >> 6;
    const float dt0 = sdt[l * 2], dt1 = sdt[l * 2 + 1];
#pragma unroll
    for (int j = 0; j < 16; j++) {
        int d = dg * 16 + j;
        float t = fmaf(dt0, __ldg(&dtw[d * 2]), fmaf(dt1, __ldg(&dtw[d * 2 + 1]), __ldg(&dtb[d])));
        float delta = (t > 20.f) ? t : log1pf(__expf(t));
        float xv = sxm2[l * 68 + d];
        float zv = sz[l * 65 + d];
        long pbase = ((long)(b * 64 + d) << 12) + lb + l;
        Pa[pbase] = make_float2(__expf(-delta), delta * xv);
        Pb[pbase] = make_float2(xv * __ldg(&Dp[d]), zv / (1.f + __expf(-zv)));
    }
}

// ============================================================
// chunked scan pass 1 (no MUFU in fast path)
// ============================================================
__global__ __launch_bounds__(256) void scan1_k(
    const float2* __restrict__ Pa, const float* __restrict__ Bm,
    const float* __restrict__ Alog,
    float* __restrict__ cA, float* __restrict__ cH)
{
    int warp = (blockIdx.x * blockDim.x + threadIdx.x) >> 5;
    int lane = threadIdx.x & 31;
    int ch = warp & (CH - 1);
    int d  = (warp >> 6) & (DIN - 1);
    int b  = warp >> 12;
    float av = expf(Alog[d * 32 + lane]);
    int e = __float2int_rn(av);
    bool ok = __all_sync(0xffffffffu,
        fabsf(av - (float)e) < 1e-4f * av && e >= 1 && e < 64);
    const float2* Pp = Pa + ((long)(b * 64 + d) << 12) + ch * LC;
    const float*  Bp = Bm + ((long)((b << 12) + ch * LC) << 5) + lane;
    float h = 0.f, ap = 1.f;
    if (ok) {
#pragma unroll 8
        for (int l = 0; l < LC; l++) {
            float2 p = Pp[l];
            float bv = Bp[l << 5];
            float dA = rpow(p.x, e);
            ap *= dA;
            h = fmaf(h, dA, p.y * bv);
        }
    } else {
        float a = -av;
        for (int l = 0; l < LC; l++) {
            float2 p = Pp[l];
            float bv = Bp[l << 5];
            float dA = __expf(-logf(p.x) * a);
            ap *= dA;
            h = fmaf(h, dA, p.y * bv);
        }
    }
    int idx = (warp << 5) + lane;
    cA[idx] = ap;
    cH[idx] = h;
}

// pass 2: sequential combine over chunks
__global__ __launch_bounds__(256) void scan2_k(
    const float* __restrict__ cA, const float* __restrict__ cH,
    float* __restrict__ hinit)
{
    int warp = (blockIdx.x * blockDim.x + threadIdx.x) >> 5;
    int lane = threadIdx.x & 31;
    int base = warp << 11;
    float h = 0.f;
#pragma unroll 4
    for (int ch = 0; ch < CH; ch++) {
        int idx = base + (ch << 5) + lane;
        float ap = cA[idx];
        float hl = cH[idx];
        hinit[idx] = h;
        h = fmaf(h, ap, hl);
    }
}

// pass 3: rescan with true h_init, emit y
__global__ __launch_bounds__(256) void scan3_k(
    const float2* __restrict__ Pa, const float2* __restrict__ Pb,
    const float* __restrict__ Bm, const float* __restrict__ Cm,
    const float* __restrict__ Alog, const float* __restrict__ hinit,
    float* __restrict__ ys)
{
    int warp = (blockIdx.x * blockDim.x + threadIdx.x) >> 5;
    int lane = threadIdx.x & 31;
    int ch = warp & (CH - 1);
    int d  = (warp >> 6) & (DIN - 1);
    int b  = warp >> 12;
    float av = expf(Alog[d * 32 + lane]);
    int e = __float2int_rn(av);
    bool ok = __all_sync(0xffffffffu,
        fabsf(av - (float)e) < 1e-4f * av && e >= 1 && e < 64);
    long pbase = ((long)(b * 64 + d) << 12) + ch * LC;
    const float2* PaP = Pa + pbase;
    const float2* PbP = Pb + pbase;
    const float*  Bp = Bm + ((long)((b << 12) + ch * LC) << 5) + lane;
    const float*  Cp = Cm + ((long)((b << 12) + ch * LC) << 5) + lane;
    float h = hinit[(warp << 5) + lane];
    float a = -av;
#pragma unroll
    for (int half = 0; half < 2; half++) {
        float yv = 0.f;
#pragma unroll
        for (int j = 0; j < 32; j++) {
            int l = half * 32 + j;
            float2 pa = PaP[l];
            float bv = Bp[l << 5];
            float cv = Cp[l << 5];
            float dA = ok ? rpow(pa.x, e) : __expf(-logf(pa.x) * a);
            h = fmaf(h, dA, pa.y * bv);
            float pr = warp_sum(h * cv);
            float2 pb = PbP[l];
            float val = (pr + pb.x) * pb.y;
            if (lane == j) yv = val;
        }
        ys[pbase + half * 32 + lane] = yv;
    }
}

// ============================================================
// out_proj: reads ys [b][d][l], writes yimg (b,c,hw)
// ============================================================
__global__ __launch_bounds__(256) void outproj_k(
    const float* __restrict__ ys, const float* __restrict__ Wo,
    float* __restrict__ oimg)
{
    __shared__ float sA[64 * 68];
    __shared__ float sW[32 * 68];
    const int g0 = blockIdx.x * 64;
    const int tid = threadIdx.x;
    const int b = g0 >> 12;
    const int lb = g0 & 4095;

    for (int i = tid; i < 64 * 64; i += 256) {
        int d = i >> 6, l = i & 63;
        sA[l * 68 + d] = ys[((long)(b * 64 + d) << 12) + lb + l];
    }
    for (int i = tid; i < 32 * 64; i += 256) {
        int c = i >> 6, k = i & 63;
        sW[c * 68 + k] = Wo[i];
    }
    __syncthreads();

    const int rg = tid & 31, cg = tid >> 5;
    const int r0 = rg * 2, c0 = cg * 4;
    float acc[2][4];
#pragma unroll
    for (int j = 0; j < 2; j++)
#pragma unroll
        for (int i = 0; i < 4; i++) acc[j][i] = 0.f;
#pragma unroll 4
    for (int k0 = 0; k0 < 64; k0 += 4) {
        float4 a4[2], w4[4];
#pragma unroll
        for (int j = 0; j < 2; j++) a4[j] = *(const float4*)&sA[(r0 + j) * 68 + k0];
#pragma unroll
        for (int i = 0; i < 4; i++) w4[i] = *(const float4*)&sW[(c0 + i) * 68 + k0];
#pragma unroll
        for (int j = 0; j < 2; j++)
#pragma unroll
            for (int i = 0; i < 4; i++) {
                acc[j][i] = fmaf(a4[j].x, w4[i].x, acc[j][i]);
                acc[j][i] = fmaf(a4[j].y, w4[i].y, acc[j][i]);
                acc[j][i] = fmaf(a4[j].z, w4[i].z, acc[j][i]);
                acc[j][i] = fmaf(a4[j].w, w4[i].w, acc[j][i]);
            }
    }
#pragma unroll
    for (int i = 0; i < 4; i++) {
        int c = c0 + i;
#pragma unroll
        for (int j = 0; j < 2; j++)
            oimg[((long)(b * 32 + c) << 12) + lb + r0 + j] = acc[j][i];
    }
}

// ============================================================
extern "C" void kernel_launch(void* const* d_in, const int* in_sizes, int n_in,
                              void* d_out, int out_size)
{
    const float* x        = (const float*)d_in[0];
    const float* conv1_w  = (const float*)d_in[1];
    const float* conv1_b  = (const float*)d_in[2];
    const float* conv2_w  = (const float*)d_in[3];
    const float* conv2_b  = (const float*)d_in[4];
    const float* ln_g     = (const float*)d_in[5];
    const float* ln_b     = (const float*)d_in[6];
    const float* in_proj_w= (const float*)d_in[7];
    const float* conv1d_w = (const float*)d_in[8];
    const float* conv1d_b = (const float*)d_in[9];
    const float* x_proj_w = (const float*)d_in[10];
    const float* dt_proj_w= (const float*)d_in[11];
    const float* dt_proj_b= (const float*)d_in[12];
    const float* A_log    = (const float*)d_in[13];
    const float* Dp       = (const float*)d_in[14];
    const float* out_proj_w=(const float*)d_in[15];
    const float* smooth_w = (const float*)d_in[16];
    const float* smooth_b = (const float*)d_in[17];
    float* out = (float*)d_out;

    float  *t_, *x2_, *xm_, *z_, *B_, *C_, *ys_, *yimg_, *cA_, *cH_, *hinit_;
    float2 *Pa_, *Pb_;
    cudaGetSymbolAddress((void**)&t_,   g_t);
    cudaGetSymbolAddress((void**)&x2_,  g_x2);
    cudaGetSymbolAddress((void**)&xm_,  g_xm);
    cudaGetSymbolAddress((void**)&z_,   g_z);
    cudaGetSymbolAddress((void**)&B_,   g_Bm);
    cudaGetSymbolAddress((void**)&C_,   g_Cm);
    cudaGetSymbolAddress((void**)&Pa_,  g_Pa);
    cudaGetSymbolAddress((void**)&Pb_,  g_Pb);
    cudaGetSymbolAddress((void**)&ys_,  g_ys);
    cudaGetSymbolAddress((void**)&yimg_,g_yimg);
    cudaGetSymbolAddress((void**)&cA_,  g_cA);
    cudaGetSymbolAddress((void**)&cH_,  g_cH);
    cudaGetSymbolAddress((void**)&hinit_, g_hinit);

    cudaFuncSetAttribute(mid_k, cudaFuncAttributeMaxDynamicSharedMemorySize,
                         MID_SMEM_FLOATS * 4);

    dim3 thr2d(16, 16);
    conv3x3_k<32, 64, 4, true, false><<<dim3(2, 2, BATCH * 16), thr2d>>>(x, conv1_w, conv1_b, nullptr, t_);
    conv3x3_k<64, 32, 2, false, true><<<dim3(2, 2, BATCH * 16), thr2d>>>(t_, conv2_w, conv2_b, x, x2_);
    inproj_k<<<GTOT / 64, 256>>>(x2_, ln_g, ln_b, in_proj_w, xm_, z_);
    mid_k<<<GTOT / 64, 256, MID_SMEM_FLOATS * 4>>>(xm_, z_, conv1d_w, conv1d_b,
        x_proj_w, dt_proj_w, dt_proj_b, Dp, B_, C_, Pa_, Pb_);
    scan1_k<<<BATCH * DIN * CH / 8, 256>>>(Pa_, B_, A_log, cA_, cH_);
    scan2_k<<<BATCH * DIN / 8, 256>>>(cA_, cH_, hinit_);
    scan3_k<<<BATCH * DIN * CH / 8, 256>>>(Pa_, Pb_, B_, C_, A_log, hinit_, ys_);
    outproj_k<<<GTOT / 64, 256>>>(ys_, out_proj_w, yimg_);
    conv3x3_k<32, 32, 2, false, false><<<dim3(2, 2, BATCH * 16), thr2d>>>(yimg_, smooth_w, smooth_b, nullptr, out);
}